// round 8
// baseline (speedup 1.0000x reference)
#include <cuda_runtime.h>

#define NEGV (-1e30f)

// Problem constants (fixed by the dataset).
#define LSEQ 512
#define PMAX 32
#define DDIM 256
#define DC   32                 // d-chunk floats staged per block
#define NC   (DDIM / DC)        // 8 d-chunks
#define TQ   2                  // token halves
#define TOK  (LSEQ / TQ)        // 256 tokens per block
#define NTHREADS 256
#define SMEM_BYTES (LSEQ * DC * 4)   // 64 KB

// Block = (batch, d-chunk, token-half). Stage inputs[b][0:512][dc*32:dc*32+32]
// into smem (64KB), then each warp sweeps (token, side) tasks:
//   lane p holds paths[token][p]; indices broadcast by shfl; gathers are
//   conflict-free LDS.32 (row stride 128B -> lane l always hits bank l).
__global__ __launch_bounds__(NTHREADS) void path_max_kernel(
    const float* __restrict__ inputs,   // [B,L,D] f32
    const int*   __restrict__ lpaths,   // [B,L,P]
    const int*   __restrict__ rpaths,   // [B,L,P]
    const int*   __restrict__ llens,    // [B,L]
    const int*   __restrict__ rlens,    // [B,L]
    const int*   __restrict__ slens,    // [B]
    float*       __restrict__ out)      // [B,L,2D]
{
    extern __shared__ float tile[];     // [512][32]

    const int bx   = blockIdx.x;
    const int b    = bx >> 4;           // / (NC*TQ)
    const int dc   = (bx >> 1) & (NC - 1);
    const int tq   = bx & (TQ - 1);
    const int tid  = threadIdx.x;
    const int w    = tid >> 5;
    const int lane = tid & 31;

    // ---- stage the tile: 4096 float4, 16 per thread, coalesced ----
    {
        const float4* __restrict__ in4 =
            reinterpret_cast<const float4*>(inputs) + (size_t)b * (LSEQ * DDIM / 4);
        float4* tile4 = reinterpret_cast<float4*>(tile);
        #pragma unroll
        for (int i = 0; i < (LSEQ * DC / 4) / NTHREADS; ++i) {
            const int e   = tid + i * NTHREADS;
            const int row = e >> 3;        // DC/4 = 8 float4 per row
            const int c4  = e & 7;
            tile4[e] = in4[row * (DDIM / 4) + dc * (DC / 4) + c4];
        }
    }
    __syncthreads();

    const int slen = __ldg(&slens[b]);

    // ---- 512 (token, side) tasks, 64 per warp ----
    for (int i = 0; i < (TOK * 2) / 8; ++i) {
        const int t     = w + 8 * i;
        const int tl    = t >> 1;
        const int side  = t & 1;
        const int token = tq * TOK + tl;
        const int gt    = b * LSEQ + token;   // global token index

        float* outp = out + (size_t)gt * (2 * DDIM) + side * DDIM + dc * DC + lane;

        if (token >= slen) { *outp = 0.f; continue; }

        const int* __restrict__ paths = side ? rpaths : lpaths;
        const int len = side ? __ldg(&rlens[gt]) : __ldg(&llens[gt]);
        const int my  = __ldg(&paths[(size_t)gt * PMAX + lane]);

        float m = NEGV;
        int idx = __shfl_sync(0xffffffffu, my, 0);
        #pragma unroll 4
        for (int p = 0; p < len; ++p) {
            const float v = tile[idx * DC + lane];
            idx = __shfl_sync(0xffffffffu, my, (p + 1) & 31);  // independent of v
            m = fmaxf(m, v);
        }
        *outp = m;
    }
}

extern "C" void kernel_launch(void* const* d_in, const int* in_sizes, int n_in,
                              void* d_out, int out_size) {
    const float* inputs = (const float*)d_in[0];
    const int*   lpaths = (const int*)d_in[1];
    const int*   rpaths = (const int*)d_in[2];
    const int*   llens  = (const int*)d_in[3];
    const int*   rlens  = (const int*)d_in[4];
    const int*   slens  = (const int*)d_in[5];

    const int B = in_sizes[5];              // sent_lens has B elements
    const int blocks = B * NC * TQ;         // 16 per batch

    static bool attr_set = false;
    if (!attr_set) {
        cudaFuncSetAttribute(path_max_kernel,
                             cudaFuncAttributeMaxDynamicSharedMemorySize,
                             SMEM_BYTES);
        attr_set = true;
    }

    path_max_kernel<<<blocks, NTHREADS, SMEM_BYTES>>>(
        inputs, lpaths, rpaths, llens, rlens, slens, (float*)d_out);
}

// round 9
// speedup vs baseline: 3.0403x; 3.0403x over previous
#include <cuda_runtime.h>

#define NEGV (-1e30f)

__device__ __forceinline__ float4 fmax4(float4 a, float4 b) {
    a.x = fmaxf(a.x, b.x);
    a.y = fmaxf(a.y, b.y);
    a.z = fmaxf(a.z, b.z);
    a.w = fmaxf(a.w, b.w);
    return a;
}

// One block (128 threads = 4 warps) per (b,l) token.
//   warp 0: left  path, d[  0:128)
//   warp 1: left  path, d[128:256)
//   warp 2: right path, d[  0:128)
//   warp 3: right path, d[128:256)
// Lane p holds paths[token][p] (P == 32); broadcast via shfls that depend
// only on register state so unrolled iterations keep ~4 loads in flight.
// __launch_bounds__(128, 16) caps regs at 32 -> 16 blocks/SM -> 64 warps/SM
// theoretical occupancy (was 12 blocks / 48 warps at 38 regs).
__global__ __launch_bounds__(128, 16) void path_max_kernel(
    const float* __restrict__ inputs,   // [B,L,D] f32, D=256
    const int*   __restrict__ lpaths,   // [B,L,P]
    const int*   __restrict__ rpaths,   // [B,L,P]
    const int*   __restrict__ llens,    // [B,L]
    const int*   __restrict__ rlens,    // [B,L]
    const int*   __restrict__ slens,    // [B]
    float*       __restrict__ out)      // [B,L,2D]
{
    constexpr int L = 512, P = 32;

    const int token = blockIdx.x;
    const int warp  = threadIdx.x >> 5;
    const int lane  = threadIdx.x & 31;
    const int side  = warp >> 1;     // 0 = left, 1 = right
    const int half  = warp & 1;      // 0 = d[0:128), 1 = d[128:256)
    const int b     = token >> 9;    // token / L
    const int l     = token & (L - 1);

    // Output quadrant: token row has 512 floats = 128 float4.
    float4* o4 = reinterpret_cast<float4*>(out)
               + (size_t)token * 128 + side * 64 + half * 32 + lane;

    if (l >= __ldg(&slens[b])) {
        *o4 = make_float4(0.f, 0.f, 0.f, 0.f);
        return;
    }

    const int* __restrict__ paths = side ? rpaths : lpaths;
    const int len = side ? __ldg(&rlens[token]) : __ldg(&llens[token]);
    const int my  = __ldg(&paths[(size_t)token * P + lane]);

    // Each row of inputs[b] is 64 float4; this warp reads float4 column
    // (half*32 + lane) of each gathered row -> coalesced 512B per LDG.128.
    const float4* __restrict__ base =
        reinterpret_cast<const float4*>(inputs)
        + (size_t)b * L * 64 + half * 32 + lane;

    float4 m = make_float4(NEGV, NEGV, NEGV, NEGV);

    int idx = __shfl_sync(0xffffffffu, my, 0);
    #pragma unroll 4
    for (int p = 0; p < len; ++p) {
        const float4 v = __ldg(base + (size_t)idx * 64);
        idx = __shfl_sync(0xffffffffu, my, (p + 1) & 31);  // independent of v
        m = fmax4(m, v);
    }

    *o4 = m;
}

extern "C" void kernel_launch(void* const* d_in, const int* in_sizes, int n_in,
                              void* d_out, int out_size) {
    const float* inputs = (const float*)d_in[0];
    const int*   lpaths = (const int*)d_in[1];
    const int*   rpaths = (const int*)d_in[2];
    const int*   llens  = (const int*)d_in[3];
    const int*   rlens  = (const int*)d_in[4];
    const int*   slens  = (const int*)d_in[5];

    const int B = in_sizes[5];      // sent_lens has B elements
    const int tokens = B * 512;     // one block per token

    path_max_kernel<<<tokens, 128>>>(inputs, lpaths, rpaths,
                                     llens, rlens, slens,
                                     (float*)d_out);
}